// round 8
// baseline (speedup 1.0000x reference)
#include <cuda_runtime.h>
#include <cstdint>

#define N_NODES 50000
#define N_EDGES 500000
#define SD 128
#define VD 3
#define HID 64
#define DEPTH 4
#define CUTOFF 5.0f

// ---------------- scratch state ----------------
__device__ float g_s[N_NODES * SD];
__device__ float g_v[N_NODES * VD * 3];
__device__ float g_zagg[N_NODES * HID];    // scatter of z = h2@Wz (C-scaled)
__device__ float g_vagg[N_NODES * VD * 3];
__device__ float g_cnt[N_NODES];
__device__ float g_inv[N_NODES];
__device__ float g_sumC[N_NODES];
__device__ float g_C[N_EDGES];
__device__ float g_ha[N_NODES * HID];      // s @ W1[0:128] + b1
__device__ float g_hb[N_NODES * HID];      // s @ W1[128:256]
__device__ float g_Wz[HID * HID];          // W3s @ Wn1b (per layer, overwritten)
__device__ float g_bz[HID];                // b3s @ Wn1b

__device__ __forceinline__ float silu(float x) {
    return x / (1.0f + __expf(-x));
}

// ---------------- packed f32x2 helpers ----------------
__device__ __forceinline__ unsigned long long pack2(float x) {
    unsigned long long p;
    unsigned int u = __float_as_uint(x);
    asm("mov.b64 %0, {%1, %1};" : "=l"(p) : "r"(u));
    return p;
}
__device__ __forceinline__ void unpack2(unsigned long long p, float& lo, float& hi) {
    unsigned int a, b;
    asm("mov.b64 {%0, %1}, %2;" : "=r"(a), "=r"(b) : "l"(p));
    lo = __uint_as_float(a);
    hi = __uint_as_float(b);
}
__device__ __forceinline__ void fma2(unsigned long long& acc,
                                     unsigned long long a, unsigned long long b) {
    asm("fma.rn.f32x2 %0, %1, %2, %0;" : "+l"(acc) : "l"(a), "l"(b));
}

__device__ __forceinline__ void red_add4(float* p, float a, float b, float c, float d) {
    asm volatile("red.global.add.v4.f32 [%0], {%1,%2,%3,%4};"
                 :: "l"(p), "f"(a), "f"(b), "f"(c), "f"(d) : "memory");
}
__device__ __forceinline__ void red_add1(float* p, float a) {
    asm volatile("red.global.add.f32 [%0], %1;" :: "l"(p), "f"(a) : "memory");
}

// ---------------- prep kernels ----------------
__global__ void init_state(const float* __restrict__ s, const float* __restrict__ v) {
    int i = blockIdx.x * blockDim.x + threadIdx.x;
    int stride = gridDim.x * blockDim.x;
    for (int k = i; k < N_NODES * SD; k += stride) g_s[k] = s[k];
    for (int k = i; k < N_NODES * VD * 3; k += stride) g_v[k] = v[k];
    for (int k = i; k < N_NODES; k += stride) { g_cnt[k] = 0.0f; g_sumC[k] = 0.0f; }
}

__global__ void prep_edges(const int* __restrict__ ei, const float* __restrict__ d) {
    int e = blockIdx.x * blockDim.x + threadIdx.x;
    if (e >= N_EDGES) return;
    int dst = ei[e];
    float dd = d[e];
    float c = 0.5f * (cospif(dd * (1.0f / CUTOFF)) + 1.0f);
    c = (dd < CUTOFF) ? c : 0.0f;
    g_C[e] = c;
    red_add1(&g_cnt[dst], 1.0f);
    red_add1(&g_sumC[dst], c);
}

__global__ void compute_inv() {
    int n = blockIdx.x * blockDim.x + threadIdx.x;
    if (n < N_NODES) g_inv[n] = 1.0f / fmaxf(g_cnt[n], 1.0f);
}

__global__ void zero_agg() {
    int i = blockIdx.x * blockDim.x + threadIdx.x;
    int stride = gridDim.x * blockDim.x;
    for (int k = i; k < N_NODES * HID; k += stride) g_zagg[k] = 0.0f;
    for (int k = i; k < N_NODES * VD * 3; k += stride) g_vagg[k] = 0.0f;
}

// ---------------- per-layer weight fold: Wz = W3s @ Wn1b, bz = b3s @ Wn1b ----
__global__ void fuse_w3(const float* __restrict__ W3, const float* __restrict__ Wn1,
                        const float* __restrict__ b3, int layer) {
    int idx = blockIdx.x * 256 + threadIdx.x;
    const float* W3g = W3 + (size_t)layer * HID * 134;
    const float* Wb  = Wn1 + (size_t)layer * 2 * SD * HID + SD * HID; // rows 128..255
    if (idx < HID * HID) {
        int k = idx >> 6, n = idx & 63;
        float acc = 0.0f;
        for (int j = 0; j < SD; j++) acc += W3g[k * 134 + j] * Wb[j * HID + n];
        g_Wz[idx] = acc;
    } else if (idx < HID * HID + HID) {
        int n = idx - HID * HID;
        const float* b3g = b3 + layer * 134;
        float acc = 0.0f;
        for (int j = 0; j < SD; j++) acc += b3g[j] * Wb[j * HID + n];
        g_bz[n] = acc;
    }
}

// ---------------- per-node W1 precompute: 2 nodes/thread, part-split blocks ----
// blockIdx.y = part (0: ha with bias, 1: hb)
__global__ __launch_bounds__(256, 2) void precompute_h(
    const float* __restrict__ W1, const float* __restrict__ b1, int layer)
{
    __shared__ float Ws[SD * HID];
    __shared__ float bs[HID];
    int part = blockIdx.y;
    const float* W1g = W1 + (size_t)layer * 257 * HID + (size_t)part * SD * HID;
    for (int i = threadIdx.x; i < SD * HID; i += 256) Ws[i] = W1g[i];
    if (threadIdx.x < HID)
        bs[threadIdx.x] = (part == 0) ? b1[layer * HID + threadIdx.x] : 0.0f;
    __syncthreads();

    int n0 = blockIdx.x * 512 + threadIdx.x;
    int n1 = n0 + 256;
    bool v1 = (n1 < N_NODES);
    float* out = (part ? g_hb : g_ha);
    const float4* x0 = reinterpret_cast<const float4*>(g_s + (size_t)n0 * SD);
    const float4* x1 = reinterpret_cast<const float4*>(g_s + (size_t)(v1 ? n1 : n0) * SD);

#pragma unroll 1
    for (int ch = 0; ch < 2; ch++) {
        unsigned long long a0[16], a1[16];
        const unsigned long long* bp = (const unsigned long long*)(bs + ch * 32);
#pragma unroll
        for (int q = 0; q < 16; q++) { a0[q] = bp[q]; a1[q] = bp[q]; }
#pragma unroll 2
        for (int kk = 0; kk < SD / 4; kk++) {
            float4 xv0 = x0[kk], xv1 = x1[kk];
            float xr0[4] = {xv0.x, xv0.y, xv0.z, xv0.w};
            float xr1[4] = {xv1.x, xv1.y, xv1.z, xv1.w};
#pragma unroll
            for (int t = 0; t < 4; t++) {
                unsigned long long p0 = pack2(xr0[t]);
                unsigned long long p1 = pack2(xr1[t]);
                const ulonglong2* wrow =
                    reinterpret_cast<const ulonglong2*>(Ws + (kk * 4 + t) * HID + ch * 32);
#pragma unroll
                for (int q = 0; q < 8; q++) {
                    ulonglong2 w = wrow[q];
                    fma2(a0[2 * q + 0], p0, w.x);
                    fma2(a0[2 * q + 1], p0, w.y);
                    fma2(a1[2 * q + 0], p1, w.x);
                    fma2(a1[2 * q + 1], p1, w.y);
                }
            }
        }
        float* o0 = out + (size_t)n0 * HID + ch * 32;
#pragma unroll
        for (int q = 0; q < 16; q++) {
            float lo, hi;
            unpack2(a0[q], lo, hi);
            o0[2 * q + 0] = lo;
            o0[2 * q + 1] = hi;
        }
        if (v1) {
            float* o1 = out + (size_t)n1 * HID + ch * 32;
#pragma unroll
            for (int q = 0; q < 16; q++) {
                float lo, hi;
                unpack2(a1[q], lo, hi);
                o1[2 * q + 0] = lo;
                o1[2 * q + 1] = hi;
            }
        }
    }
}

// ---------------- edge kernel: 128-edge tile, smem-staged GEMMs ----------------
// Phase A: h1[64][128] in smem (silu(ha[dst]+hb[src]+d*wd))
// Phase B: h2 = silu(h1 @ W2 + b2) -> smem [64][128]
// Phase C: z = h2 @ Wz, scatter z*C to g_zagg (64 wide)
// Phase D: g6 = gv/gr cols, vector scatter
#define ETILE 128
__global__ __launch_bounds__(256, 2) void edge_kernel(
    const int* __restrict__ ei, const float* __restrict__ d, const float* __restrict__ r,
    const float* __restrict__ W1, const float* __restrict__ W2,
    const float* __restrict__ b2, const float* __restrict__ W3,
    const float* __restrict__ b3, int layer)
{
    extern __shared__ float sm[];
    float* W2s  = sm;                    // 4096
    float* Wzs  = W2s + HID * HID;       // 4096
    float* W3vs = Wzs + HID * HID;       // 64*8
    float* wds  = W3vs + HID * 8;        // 64
    float* b2s  = wds + HID;             // 64
    float* b3vs = b2s + HID;             // 8
    float* Cs   = b3vs + 8;              // 128
    float* h1s  = Cs + ETILE;            // 64*128
    float* h2s  = h1s + HID * ETILE;     // 64*128
    int*   dsts = (int*)(h2s + HID * ETILE); // 128
    int*   srcs = dsts + ETILE;              // 128

    const float* W2g = W2 + (size_t)layer * HID * HID;
    const float* W3g = W3 + (size_t)layer * HID * 134;
    const float* b3g = b3 + (size_t)layer * 134;
    const float* wdg = W1 + (size_t)layer * 257 * HID + 256 * HID;

    int tid = threadIdx.x;
    for (int i = tid; i < HID * HID; i += 256) { W2s[i] = W2g[i]; Wzs[i] = g_Wz[i]; }
    for (int i = tid; i < HID * 6; i += 256) {
        int k = i / 6, j = i - k * 6;
        W3vs[k * 8 + j] = W3g[k * 134 + SD + j];
    }
    if (tid < HID) { wds[tid] = wdg[tid]; b2s[tid] = b2[layer * HID + tid]; }
    if (tid < 6) b3vs[tid] = b3g[SD + tid];
    __syncthreads();

    // ---- Phase A ----
    {
        int e = tid & (ETILE - 1);
        int half = tid >> 7;
        int ge = blockIdx.x * ETILE + e;
        bool ok = (ge < N_EDGES);
        int dst = ok ? ei[ge] : 0;
        int src = ok ? ei[N_EDGES + ge] : 0;
        if (half == 0) {
            dsts[e] = dst;
            Cs[e] = ok ? g_C[ge] : 0.0f;
        } else {
            srcs[e] = src;
        }
        if (ok) {
            float de = d[ge];
            const float4* ap = reinterpret_cast<const float4*>(g_ha + (size_t)dst * HID + half * 32);
            const float4* bp = reinterpret_cast<const float4*>(g_hb + (size_t)src * HID + half * 32);
            const float4* wp = reinterpret_cast<const float4*>(wds + half * 32);
#pragma unroll
            for (int q = 0; q < 8; q++) {
                float4 a = ap[q], b = bp[q], w = wp[q];
                int j = half * 32 + q * 4;
                h1s[(j + 0) * ETILE + e] = silu(fmaf(de, w.x, a.x + b.x));
                h1s[(j + 1) * ETILE + e] = silu(fmaf(de, w.y, a.y + b.y));
                h1s[(j + 2) * ETILE + e] = silu(fmaf(de, w.z, a.z + b.z));
                h1s[(j + 3) * ETILE + e] = silu(fmaf(de, w.w, a.w + b.w));
            }
        } else {
#pragma unroll
            for (int q = 0; q < 32; q++)
                h1s[(half * 32 + q) * ETILE + e] = 0.0f;
        }
    }
    __syncthreads();

    int tn = tid & 7;        // 8 n-tiles of 8
    int tm = tid >> 3;       // 32 m-tiles of 4
    int n0 = tn * 8;
    int m0 = tm * 4;

    // ---- Phase B: GEMM1 (h1 @ W2 + b2, silu) -> h2s ----
    {
        unsigned long long acc[4][4];
        const unsigned long long* binit = (const unsigned long long*)(b2s + n0);
#pragma unroll
        for (int mi = 0; mi < 4; mi++)
#pragma unroll
            for (int q = 0; q < 4; q++) acc[mi][q] = binit[q];

#pragma unroll 4
        for (int k = 0; k < HID; k++) {
            float4 a = *reinterpret_cast<const float4*>(h1s + k * ETILE + m0);
            const ulonglong2* wr = reinterpret_cast<const ulonglong2*>(W2s + k * HID + n0);
            ulonglong2 w0 = wr[0], w1 = wr[1];
            float ar[4] = {a.x, a.y, a.z, a.w};
#pragma unroll
            for (int mi = 0; mi < 4; mi++) {
                unsigned long long am = pack2(ar[mi]);
                fma2(acc[mi][0], am, w0.x);
                fma2(acc[mi][1], am, w0.y);
                fma2(acc[mi][2], am, w1.x);
                fma2(acc[mi][3], am, w1.y);
            }
        }
#pragma unroll
        for (int q = 0; q < 4; q++) {
            float lo[4], hi[4];
#pragma unroll
            for (int mi = 0; mi < 4; mi++) unpack2(acc[mi][q], lo[mi], hi[mi]);
            float4 vlo = {silu(lo[0]), silu(lo[1]), silu(lo[2]), silu(lo[3])};
            float4 vhi = {silu(hi[0]), silu(hi[1]), silu(hi[2]), silu(hi[3])};
            *reinterpret_cast<float4*>(h2s + (n0 + 2 * q + 0) * ETILE + m0) = vlo;
            *reinterpret_cast<float4*>(h2s + (n0 + 2 * q + 1) * ETILE + m0) = vhi;
        }
    }
    __syncthreads();

    // ---- Phase C: GEMM2 (h2 @ Wz), scatter z*C ----
    {
        unsigned long long acc[4][4];
#pragma unroll
        for (int mi = 0; mi < 4; mi++)
#pragma unroll
            for (int q = 0; q < 4; q++) acc[mi][q] = 0ULL;

#pragma unroll 4
        for (int k = 0; k < HID; k++) {
            float4 a = *reinterpret_cast<const float4*>(h2s + k * ETILE + m0);
            const ulonglong2* wr = reinterpret_cast<const ulonglong2*>(Wzs + k * HID + n0);
            ulonglong2 w0 = wr[0], w1 = wr[1];
            float ar[4] = {a.x, a.y, a.z, a.w};
#pragma unroll
            for (int mi = 0; mi < 4; mi++) {
                unsigned long long am = pack2(ar[mi]);
                fma2(acc[mi][0], am, w0.x);
                fma2(acc[mi][1], am, w0.y);
                fma2(acc[mi][2], am, w1.x);
                fma2(acc[mi][3], am, w1.y);
            }
        }
#pragma unroll
        for (int mi = 0; mi < 4; mi++) {
            int e = m0 + mi;
            float C = Cs[e];
            int dst = dsts[e];
            float z[8];
#pragma unroll
            for (int q = 0; q < 4; q++) {
                float lo, hi;
                unpack2(acc[mi][q], lo, hi);
                z[2 * q + 0] = lo * C;
                z[2 * q + 1] = hi * C;
            }
            float* zp = g_zagg + (size_t)dst * HID + n0;
            red_add4(zp, z[0], z[1], z[2], z[3]);
            red_add4(zp + 4, z[4], z[5], z[6], z[7]);
        }
    }

    // ---- Phase D: gv/gr + vector scatter (threads 0..127, one edge each) ----
    if (tid < ETILE) {
        int e = tid;
        int ge = blockIdx.x * ETILE + e;
        float C = Cs[e];
        float g6[6];
#pragma unroll
        for (int j = 0; j < 6; j++) g6[j] = b3vs[j];
#pragma unroll 4
        for (int k = 0; k < HID; k++) {
            float hv = h2s[k * ETILE + e];
#pragma unroll
            for (int j = 0; j < 6; j++) g6[j] += hv * W3vs[k * 8 + j];
        }
        float rr0 = 0.0f, rr1 = 0.0f, rr2 = 0.0f;
        if (ge < N_EDGES) {
            rr0 = r[ge * 3 + 0]; rr1 = r[ge * 3 + 1]; rr2 = r[ge * 3 + 2];
        }
        int src = srcs[e], dst = dsts[e];
        const float* vs = g_v + (size_t)src * 9;
        float* vdp = g_vagg + (size_t)dst * 9;
#pragma unroll
        for (int a = 0; a < 3; a++) {
            float gva = g6[a] * C, gra = g6[3 + a] * C;
            red_add1(vdp + a * 3 + 0, vs[a * 3 + 0] * gva + rr0 * gra);
            red_add1(vdp + a * 3 + 1, vs[a * 3 + 1] * gva + rr1 * gra);
            red_add1(vdp + a * 3 + 2, vs[a * 3 + 2] * gva + rr2 * gra);
        }
    }
}

// ---------------- fused node MLP + residual (z-folded, K=128 first GEMM) ----
__global__ __launch_bounds__(256, 2) void node_kernel(
    const float* __restrict__ Wn1, const float* __restrict__ bn1,
    const float* __restrict__ Wn2, const float* __restrict__ bn2, int layer)
{
    extern __shared__ float sm[];
    float* W1s = sm;                 // 128*64 (Wn1 rows 0..127 only)
    float* W2s = W1s + SD * HID;     // 64*128
    float* b1s = W2s + HID * SD;     // 64
    float* b2s = b1s + HID;          // 128
    float* bzs = b2s + SD;           // 64

    const float* W1g = Wn1 + (size_t)layer * 2 * SD * HID;      // first 128 rows
    const float* W2g = Wn2 + (size_t)layer * HID * SD;
    for (int i = threadIdx.x; i < SD * HID; i += 256) W1s[i] = W1g[i];
    for (int i = threadIdx.x; i < HID * SD; i += 256) W2s[i] = W2g[i];
    if (threadIdx.x < HID) {
        b1s[threadIdx.x] = bn1[layer * HID + threadIdx.x];
        bzs[threadIdx.x] = g_bz[threadIdx.x];
    }
    if (threadIdx.x < SD) b2s[threadIdx.x] = bn2[layer * SD + threadIdx.x];
    __syncthreads();

    int n = blockIdx.x * blockDim.x + threadIdx.x;
    if (n >= N_NODES) return;

    const float4* xs = reinterpret_cast<const float4*>(g_s + (size_t)n * SD);
    float sumC = g_sumC[n];
    const unsigned long long* zag = (const unsigned long long*)(g_zagg + (size_t)n * HID);

    float u[HID];
#pragma unroll 1
    for (int ch = 0; ch < 2; ch++) {
        unsigned long long acc[16];
        const unsigned long long* bp = (const unsigned long long*)(b1s + ch * 32);
#pragma unroll
        for (int q = 0; q < 16; q++) acc[q] = bp[q];
#pragma unroll 4
        for (int kk = 0; kk < SD / 4; kk++) {
            float4 xv = xs[kk];
            float xr[4] = {xv.x, xv.y, xv.z, xv.w};
#pragma unroll
            for (int t = 0; t < 4; t++) {
                unsigned long long xk2 = pack2(xr[t]);
                const ulonglong2* wrow =
                    reinterpret_cast<const ulonglong2*>(W1s + (kk * 4 + t) * HID + ch * 32);
#pragma unroll
                for (int q = 0; q < 8; q++) {
                    ulonglong2 w = wrow[q];
                    fma2(acc[2 * q + 0], xk2, w.x);
                    fma2(acc[2 * q + 1], xk2, w.y);
                }
            }
        }
#pragma unroll
        for (int q = 0; q < 16; q++) {
            float lo, hi;
            unpack2(acc[q], lo, hi);
            float zl, zh;
            unpack2(zag[ch * 16 + q], zl, zh);
            int j = ch * 32 + 2 * q;
            u[j + 0] = silu(lo + zl + sumC * bzs[j + 0]);
            u[j + 1] = silu(hi + zh + sumC * bzs[j + 1]);
        }
    }

    float* sp = g_s + (size_t)n * SD;
#pragma unroll 1
    for (int c = 0; c < 4; c++) {
        unsigned long long acc[16];
        const unsigned long long* bp = (const unsigned long long*)(b2s + c * 32);
#pragma unroll
        for (int q = 0; q < 16; q++) acc[q] = bp[q];
#pragma unroll 4
        for (int k = 0; k < HID; k++) {
            unsigned long long hk2 = pack2(u[k]);
            const ulonglong2* wrow = reinterpret_cast<const ulonglong2*>(W2s + k * SD + c * 32);
#pragma unroll
            for (int q = 0; q < 8; q++) {
                ulonglong2 w = wrow[q];
                fma2(acc[2 * q + 0], hk2, w.x);
                fma2(acc[2 * q + 1], hk2, w.y);
            }
        }
#pragma unroll
        for (int q = 0; q < 16; q++) {
            float lo, hi;
            unpack2(acc[q], lo, hi);
            sp[c * 32 + 2 * q + 0] += lo;
            sp[c * 32 + 2 * q + 1] += hi;
        }
    }

    float inv = g_inv[n];
    float* vp = g_v + (size_t)n * 9;
    const float* va = g_vagg + (size_t)n * 9;
#pragma unroll
    for (int i = 0; i < 9; i++) vp[i] += va[i] * inv;
}

__global__ void write_out(float* __restrict__ out) {
    int i = blockIdx.x * blockDim.x + threadIdx.x;
    int stride = gridDim.x * blockDim.x;
    for (int k = i; k < N_NODES * SD; k += stride) out[k] = g_s[k];
    for (int k = i; k < N_NODES * VD * 3; k += stride) out[N_NODES * SD + k] = g_v[k];
}

// ---------------- launch ----------------
extern "C" void kernel_launch(void* const* d_in, const int* in_sizes, int n_in,
                              void* d_out, int out_size) {
    const float* s   = (const float*)d_in[0];
    const float* v   = (const float*)d_in[1];
    const int*   ei  = (const int*)d_in[2];
    const float* d   = (const float*)d_in[3];
    const float* r   = (const float*)d_in[4];
    const float* W1  = (const float*)d_in[5];
    const float* b1  = (const float*)d_in[6];
    const float* W2  = (const float*)d_in[7];
    const float* b2  = (const float*)d_in[8];
    const float* W3  = (const float*)d_in[9];
    const float* b3  = (const float*)d_in[10];
    const float* Wn1 = (const float*)d_in[11];
    const float* bn1 = (const float*)d_in[12];
    const float* Wn2 = (const float*)d_in[13];
    const float* bn2 = (const float*)d_in[14];
    float* out = (float*)d_out;

    const int edge_smem = (HID * HID * 2 + HID * 8 + HID + HID + 8 + ETILE
                           + HID * ETILE * 2) * 4 + ETILE * 2 * 4;
    const int node_smem = (SD * HID + HID * SD + HID + SD + HID) * 4;
    cudaFuncSetAttribute(edge_kernel, cudaFuncAttributeMaxDynamicSharedMemorySize, edge_smem);
    cudaFuncSetAttribute(node_kernel, cudaFuncAttributeMaxDynamicSharedMemorySize, node_smem);

    init_state<<<1024, 256>>>(s, v);
    prep_edges<<<(N_EDGES + 255) / 256, 256>>>(ei, d);
    compute_inv<<<(N_NODES + 255) / 256, 256>>>();

    dim3 pre_grid((N_NODES + 511) / 512, 2);
    const int edge_blocks = (N_EDGES + ETILE - 1) / ETILE;

    for (int l = 0; l < DEPTH; l++) {
        fuse_w3<<<(HID * HID + HID + 255) / 256, 256>>>(W3, Wn1, b3, l);
        precompute_h<<<pre_grid, 256>>>(W1, b1, l);
        zero_agg<<<1024, 256>>>();
        edge_kernel<<<edge_blocks, 256, edge_smem>>>(ei, d, r, W1, W2, b2, W3, b3, l);
        node_kernel<<<(N_NODES + 255) / 256, 256, node_smem>>>(Wn1, bn1, Wn2, bn2, l);
    }
    write_out<<<1024, 256>>>(out);
}

// round 10
// speedup vs baseline: 1.7083x; 1.7083x over previous
#include <cuda_runtime.h>
#include <cstdint>

#define N_NODES 50000
#define N_EDGES 500000
#define SD 128
#define VD 3
#define HID 64
#define DEPTH 4
#define CUTOFF 5.0f

// ---------------- scratch state ----------------
__device__ float g_s[N_NODES * SD];
__device__ float g_v[N_NODES * VD * 3];
__device__ float g_zagg[N_NODES * HID];    // scatter of z = C * (h2 @ Wz)
__device__ float g_vagg[N_NODES * VD * 3];
__device__ float g_cnt[N_NODES];
__device__ float g_inv[N_NODES];
__device__ float g_sumC[N_NODES];
__device__ float g_C[N_EDGES];
__device__ float g_ha[N_NODES * HID];      // s @ W1[0:128] + b1
__device__ float g_hb[N_NODES * HID];      // s @ W1[128:256]
__device__ float g_Wz[DEPTH * HID * HID];  // W3s @ Wn1b (all layers)
__device__ float g_bz[DEPTH * HID];        // b3s @ Wn1b

__device__ __forceinline__ float silu(float x) {
    return x / (1.0f + __expf(-x));
}

// ---------------- packed f32x2 helpers ----------------
__device__ __forceinline__ unsigned long long pack2(float x) {
    unsigned long long p;
    unsigned int u = __float_as_uint(x);
    asm("mov.b64 %0, {%1, %1};" : "=l"(p) : "r"(u));
    return p;
}
__device__ __forceinline__ void unpack2(unsigned long long p, float& lo, float& hi) {
    unsigned int a, b;
    asm("mov.b64 {%0, %1}, %2;" : "=r"(a), "=r"(b) : "l"(p));
    lo = __uint_as_float(a);
    hi = __uint_as_float(b);
}
__device__ __forceinline__ void fma2(unsigned long long& acc,
                                     unsigned long long a, unsigned long long b) {
    asm("fma.rn.f32x2 %0, %1, %2, %0;" : "+l"(acc) : "l"(a), "l"(b));
}
__device__ __forceinline__ unsigned long long mul2(unsigned long long a,
                                                   unsigned long long b) {
    unsigned long long d;
    asm("mul.rn.f32x2 %0, %1, %2;" : "=l"(d) : "l"(a), "l"(b));
    return d;
}

__device__ __forceinline__ void red_add4(float* p, float a, float b, float c, float d) {
    asm volatile("red.global.add.v4.f32 [%0], {%1,%2,%3,%4};"
                 :: "l"(p), "f"(a), "f"(b), "f"(c), "f"(d) : "memory");
}
__device__ __forceinline__ void red_add1(float* p, float a) {
    asm volatile("red.global.add.f32 [%0], %1;" :: "l"(p), "f"(a) : "memory");
}

// ---------------- prep kernels ----------------
__global__ void init_state(const float* __restrict__ s, const float* __restrict__ v) {
    int i = blockIdx.x * blockDim.x + threadIdx.x;
    int stride = gridDim.x * blockDim.x;
    for (int k = i; k < N_NODES * SD; k += stride) g_s[k] = s[k];
    for (int k = i; k < N_NODES * VD * 3; k += stride) g_v[k] = v[k];
    for (int k = i; k < N_NODES; k += stride) { g_cnt[k] = 0.0f; g_sumC[k] = 0.0f; }
}

__global__ void prep_edges(const int* __restrict__ ei, const float* __restrict__ d) {
    int e = blockIdx.x * blockDim.x + threadIdx.x;
    if (e >= N_EDGES) return;
    int dst = ei[e];
    float dd = d[e];
    float c = 0.5f * (cospif(dd * (1.0f / CUTOFF)) + 1.0f);
    c = (dd < CUTOFF) ? c : 0.0f;
    g_C[e] = c;
    red_add1(&g_cnt[dst], 1.0f);
    red_add1(&g_sumC[dst], c);
}

__global__ void compute_inv() {
    int n = blockIdx.x * blockDim.x + threadIdx.x;
    if (n < N_NODES) g_inv[n] = 1.0f / fmaxf(g_cnt[n], 1.0f);
}

__global__ void zero_agg() {
    int i = blockIdx.x * blockDim.x + threadIdx.x;
    int stride = gridDim.x * blockDim.x;
    for (int k = i; k < N_NODES * HID; k += stride) g_zagg[k] = 0.0f;
    for (int k = i; k < N_NODES * VD * 3; k += stride) g_vagg[k] = 0.0f;
}

// ---------------- all-layer weight fold: Wz = W3s @ Wn1b, bz = b3s @ Wn1b ----
__global__ void fuse_w3_all(const float* __restrict__ W3, const float* __restrict__ Wn1,
                            const float* __restrict__ b3) {
    int idx = blockIdx.x * 256 + threadIdx.x;
    const int per_layer = HID * HID + HID;
    int layer = idx / per_layer;
    if (layer >= DEPTH) return;
    int li = idx - layer * per_layer;
    const float* W3g = W3 + (size_t)layer * HID * 134;
    const float* Wb  = Wn1 + (size_t)layer * 2 * SD * HID + SD * HID; // rows 128..255
    if (li < HID * HID) {
        int k = li >> 6, n = li & 63;
        float acc = 0.0f;
        for (int j = 0; j < SD; j++) acc += W3g[k * 134 + j] * Wb[j * HID + n];
        g_Wz[layer * HID * HID + li] = acc;
    } else {
        int n = li - HID * HID;
        const float* b3g = b3 + layer * 134;
        float acc = 0.0f;
        for (int j = 0; j < SD; j++) acc += b3g[j] * Wb[j * HID + n];
        g_bz[layer * HID + n] = acc;
    }
}

// ---------------- per-node W1 precompute (R5 structure, measured-good) ------
__global__ __launch_bounds__(256) void precompute_h(
    const float* __restrict__ W1, const float* __restrict__ b1, int layer)
{
    extern __shared__ float sm[];
    float* W1s = sm;              // 256*64
    float* b1s = W1s + 256 * HID; // 64

    const float* W1g = W1 + (size_t)layer * 257 * HID;
    for (int i = threadIdx.x; i < 256 * HID; i += blockDim.x) W1s[i] = W1g[i];
    for (int i = threadIdx.x; i < HID; i += blockDim.x) b1s[i] = b1[layer * HID + i];
    __syncthreads();

    int n = blockIdx.x * blockDim.x + threadIdx.x;
    if (n >= N_NODES) return;

    const float4* xs = reinterpret_cast<const float4*>(g_s + (size_t)n * SD);

    // ---- ha ----
    unsigned long long acc[32];
    {
        const unsigned long long* bp = (const unsigned long long*)b1s;
#pragma unroll
        for (int q = 0; q < 32; q++) acc[q] = bp[q];
    }
#pragma unroll 4
    for (int kk = 0; kk < SD / 4; kk++) {
        float4 xv = xs[kk];
        float xr[4] = {xv.x, xv.y, xv.z, xv.w};
#pragma unroll
        for (int t = 0; t < 4; t++) {
            unsigned long long xk2 = pack2(xr[t]);
            const ulonglong2* wrow = reinterpret_cast<const ulonglong2*>(W1s + (kk * 4 + t) * HID);
#pragma unroll
            for (int q = 0; q < 16; q++) {
                ulonglong2 w = wrow[q];
                fma2(acc[2 * q + 0], xk2, w.x);
                fma2(acc[2 * q + 1], xk2, w.y);
            }
        }
    }
    {
        float* hap = g_ha + (size_t)n * HID;
#pragma unroll
        for (int q = 0; q < 32; q++) {
            float lo, hi;
            unpack2(acc[q], lo, hi);
            hap[2 * q + 0] = lo;
            hap[2 * q + 1] = hi;
        }
    }

    // ---- hb ----
#pragma unroll
    for (int q = 0; q < 32; q++) acc[q] = 0ULL;
#pragma unroll 4
    for (int kk = 0; kk < SD / 4; kk++) {
        float4 xv = xs[kk];
        float xr[4] = {xv.x, xv.y, xv.z, xv.w};
#pragma unroll
        for (int t = 0; t < 4; t++) {
            unsigned long long xk2 = pack2(xr[t]);
            const ulonglong2* wrow = reinterpret_cast<const ulonglong2*>(W1s + (SD + kk * 4 + t) * HID);
#pragma unroll
            for (int q = 0; q < 16; q++) {
                ulonglong2 w = wrow[q];
                fma2(acc[2 * q + 0], xk2, w.x);
                fma2(acc[2 * q + 1], xk2, w.y);
            }
        }
    }
    {
        float* hbp = g_hb + (size_t)n * HID;
#pragma unroll
        for (int q = 0; q < 32; q++) {
            float lo, hi;
            unpack2(acc[q], lo, hi);
            hbp[2 * q + 0] = lo;
            hbp[2 * q + 1] = hi;
        }
    }
}

// ---------------- fused edge MLP + scatter (per-thread, Wz-folded) ----------
__global__ __launch_bounds__(256, 2) void edge_kernel(
    const int* __restrict__ ei, const float* __restrict__ d, const float* __restrict__ r,
    const float* __restrict__ W1, const float* __restrict__ W2,
    const float* __restrict__ b2, const float* __restrict__ W3,
    const float* __restrict__ b3, int layer)
{
    extern __shared__ float sm[];
    float* W2s  = sm;                 // 64*64
    float* Wzs  = W2s + HID * HID;    // 64*64
    float* W3vs = Wzs + HID * HID;    // 64*8 (6 used, padded)
    float* wds  = W3vs + HID * 8;     // 64
    float* b2s  = wds + HID;          // 64
    float* b3vs = b2s + HID;          // 8

    const float* W2g = W2 + (size_t)layer * HID * HID;
    const float* W3g = W3 + (size_t)layer * HID * 134;
    const float* b3g = b3 + (size_t)layer * 134;
    const float* wdg = W1 + (size_t)layer * 257 * HID + 256 * HID;
    const float* Wzg = g_Wz + (size_t)layer * HID * HID;

    int tid = threadIdx.x;
    for (int i = tid; i < HID * HID; i += 256) { W2s[i] = W2g[i]; Wzs[i] = Wzg[i]; }
    for (int i = tid; i < HID * 6; i += 256) {
        int k = i / 6, j = i - k * 6;
        W3vs[k * 8 + j] = W3g[k * 134 + SD + j];
    }
    if (tid < HID) { wds[tid] = wdg[tid]; b2s[tid] = b2[layer * HID + tid]; }
    if (tid < 6) b3vs[tid] = b3g[SD + tid];
    __syncthreads();

    int e = blockIdx.x * 256 + tid;
    if (e >= N_EDGES) return;

    int dst = ei[e];
    int src = ei[N_EDGES + e];
    float C = g_C[e];
    float de = d[e];

    // ---- h1 = silu(ha[dst] + hb[src] + d*wd) ----
    float h1[HID];
    {
        const float4* ap = reinterpret_cast<const float4*>(g_ha + (size_t)dst * HID);
        const float4* bp = reinterpret_cast<const float4*>(g_hb + (size_t)src * HID);
        const float4* wp = reinterpret_cast<const float4*>(wds);
#pragma unroll
        for (int q = 0; q < HID / 4; q++) {
            float4 a = ap[q], b = bp[q], w = wp[q];
            h1[4 * q + 0] = silu(fmaf(de, w.x, a.x + b.x));
            h1[4 * q + 1] = silu(fmaf(de, w.y, a.y + b.y));
            h1[4 * q + 2] = silu(fmaf(de, w.z, a.z + b.z));
            h1[4 * q + 3] = silu(fmaf(de, w.w, a.w + b.w));
        }
    }

    // ---- h2 = silu(h1 @ W2 + b2), two 32-output halves ----
    float h2[HID];
#pragma unroll 1
    for (int half = 0; half < 2; half++) {
        unsigned long long acc[16];
        const unsigned long long* bp = (const unsigned long long*)(b2s + half * 32);
#pragma unroll
        for (int q = 0; q < 16; q++) acc[q] = bp[q];
#pragma unroll 4
        for (int k = 0; k < HID; k++) {
            unsigned long long hk2 = pack2(h1[k]);
            const ulonglong2* wrow = reinterpret_cast<const ulonglong2*>(W2s + k * HID + half * 32);
#pragma unroll
            for (int q = 0; q < 8; q++) {
                ulonglong2 w = wrow[q];
                fma2(acc[2 * q + 0], hk2, w.x);
                fma2(acc[2 * q + 1], hk2, w.y);
            }
        }
#pragma unroll
        for (int q = 0; q < 16; q++) {
            float lo, hi;
            unpack2(acc[q], lo, hi);
            h2[half * 32 + 2 * q + 0] = silu(lo);
            h2[half * 32 + 2 * q + 1] = silu(hi);
        }
    }

    // ---- z = h2 @ Wz (64 wide), scatter C*z; gv/gr fused into first half ----
    unsigned long long C2 = pack2(C);
    float* zbase = g_zagg + (size_t)dst * HID;

    unsigned long long g01 = ((const unsigned long long*)b3vs)[0];
    unsigned long long g23 = ((const unsigned long long*)b3vs)[1];
    unsigned long long g45 = ((const unsigned long long*)b3vs)[2];

#pragma unroll 1
    for (int half = 0; half < 2; half++) {
        unsigned long long acc[16];
#pragma unroll
        for (int q = 0; q < 16; q++) acc[q] = 0ULL;

        if (half == 0) {
#pragma unroll 4
            for (int k = 0; k < HID; k++) {
                unsigned long long hk2 = pack2(h2[k]);
                const ulonglong2* wrow = reinterpret_cast<const ulonglong2*>(Wzs + k * HID);
#pragma unroll
                for (int q = 0; q < 8; q++) {
                    ulonglong2 w = wrow[q];
                    fma2(acc[2 * q + 0], hk2, w.x);
                    fma2(acc[2 * q + 1], hk2, w.y);
                }
                const unsigned long long* gw = (const unsigned long long*)(W3vs + k * 8);
                fma2(g01, hk2, gw[0]);
                fma2(g23, hk2, gw[1]);
                fma2(g45, hk2, gw[2]);
            }
        } else {
#pragma unroll 4
            for (int k = 0; k < HID; k++) {
                unsigned long long hk2 = pack2(h2[k]);
                const ulonglong2* wrow = reinterpret_cast<const ulonglong2*>(Wzs + k * HID + 32);
#pragma unroll
                for (int q = 0; q < 8; q++) {
                    ulonglong2 w = wrow[q];
                    fma2(acc[2 * q + 0], hk2, w.x);
                    fma2(acc[2 * q + 1], hk2, w.y);
                }
            }
        }
#pragma unroll
        for (int q = 0; q < 8; q++) {
            unsigned long long p0 = mul2(acc[2 * q + 0], C2);
            unsigned long long p1 = mul2(acc[2 * q + 1], C2);
            float a0, a1, a2, a3;
            unpack2(p0, a0, a1);
            unpack2(p1, a2, a3);
            red_add4(zbase + half * 32 + q * 4, a0, a1, a2, a3);
        }
    }

    // ---- vector scatter ----
    float g6[6];
    unpack2(g01, g6[0], g6[1]);
    unpack2(g23, g6[2], g6[3]);
    unpack2(g45, g6[4], g6[5]);

    float rr0 = r[e * 3 + 0], rr1 = r[e * 3 + 1], rr2 = r[e * 3 + 2];
    const float* vs = g_v + (size_t)src * 9;
    float* vdp = g_vagg + (size_t)dst * 9;
#pragma unroll
    for (int a = 0; a < 3; a++) {
        float gva = g6[a] * C, gra = g6[3 + a] * C;
        red_add1(vdp + a * 3 + 0, vs[a * 3 + 0] * gva + rr0 * gra);
        red_add1(vdp + a * 3 + 1, vs[a * 3 + 1] * gva + rr1 * gra);
        red_add1(vdp + a * 3 + 2, vs[a * 3 + 2] * gva + rr2 * gra);
    }
}

// ---------------- fused node MLP + residual (z-folded, K=128 first GEMM) ----
__global__ __launch_bounds__(256, 2) void node_kernel(
    const float* __restrict__ Wn1, const float* __restrict__ bn1,
    const float* __restrict__ Wn2, const float* __restrict__ bn2, int layer)
{
    extern __shared__ float sm[];
    float* W1s = sm;                 // 128*64 (Wn1 rows 0..127 only)
    float* W2s = W1s + SD * HID;     // 64*128
    float* b1s = W2s + HID * SD;     // 64
    float* b2s = b1s + HID;          // 128
    float* bzs = b2s + SD;           // 64

    const float* W1g = Wn1 + (size_t)layer * 2 * SD * HID;   // first 128 rows
    const float* W2g = Wn2 + (size_t)layer * HID * SD;
    for (int i = threadIdx.x; i < SD * HID; i += 256) W1s[i] = W1g[i];
    for (int i = threadIdx.x; i < HID * SD; i += 256) W2s[i] = W2g[i];
    if (threadIdx.x < HID) {
        b1s[threadIdx.x] = bn1[layer * HID + threadIdx.x];
        bzs[threadIdx.x] = g_bz[layer * HID + threadIdx.x];
    }
    if (threadIdx.x < SD) b2s[threadIdx.x] = bn2[layer * SD + threadIdx.x];
    __syncthreads();

    int n = blockIdx.x * blockDim.x + threadIdx.x;
    if (n >= N_NODES) return;

    const float4* xs = reinterpret_cast<const float4*>(g_s + (size_t)n * SD);
    float sumC = g_sumC[n];
    const unsigned long long* zag = (const unsigned long long*)(g_zagg + (size_t)n * HID);

    // ---- u = silu(s@Wn1a + bn1 + zagg + sumC*bz) ----
    unsigned long long up[32];
    {
        const unsigned long long* bp = (const unsigned long long*)b1s;
#pragma unroll
        for (int q = 0; q < 32; q++) up[q] = bp[q];
    }
#pragma unroll 4
    for (int kk = 0; kk < SD / 4; kk++) {
        float4 xv = xs[kk];
        float xr[4] = {xv.x, xv.y, xv.z, xv.w};
#pragma unroll
        for (int t = 0; t < 4; t++) {
            unsigned long long xk2 = pack2(xr[t]);
            const ulonglong2* wrow = reinterpret_cast<const ulonglong2*>(W1s + (kk * 4 + t) * HID);
#pragma unroll
            for (int q = 0; q < 16; q++) {
                ulonglong2 w = wrow[q];
                fma2(up[2 * q + 0], xk2, w.x);
                fma2(up[2 * q + 1], xk2, w.y);
            }
        }
    }
    float u[HID];
#pragma unroll
    for (int q = 0; q < 32; q++) {
        float lo, hi;
        unpack2(up[q], lo, hi);
        float zl, zh;
        unpack2(zag[q], zl, zh);
        u[2 * q + 0] = silu(lo + zl + sumC * bzs[2 * q + 0]);
        u[2 * q + 1] = silu(hi + zh + sumC * bzs[2 * q + 1]);
    }

    float* sp = g_s + (size_t)n * SD;
#pragma unroll 1
    for (int c = 0; c < 4; c++) {
        unsigned long long acc[16];
        const unsigned long long* bp = (const unsigned long long*)(b2s + c * 32);
#pragma unroll
        for (int q = 0; q < 16; q++) acc[q] = bp[q];
#pragma unroll 4
        for (int k = 0; k < HID; k++) {
            unsigned long long hk2 = pack2(u[k]);
            const ulonglong2* wrow = reinterpret_cast<const ulonglong2*>(W2s + k * SD + c * 32);
#pragma unroll
            for (int q = 0; q < 8; q++) {
                ulonglong2 w = wrow[q];
                fma2(acc[2 * q + 0], hk2, w.x);
                fma2(acc[2 * q + 1], hk2, w.y);
            }
        }
#pragma unroll
        for (int q = 0; q < 16; q++) {
            float lo, hi;
            unpack2(acc[q], lo, hi);
            sp[c * 32 + 2 * q + 0] += lo;
            sp[c * 32 + 2 * q + 1] += hi;
        }
    }

    float inv = g_inv[n];
    float* vp = g_v + (size_t)n * 9;
    const float* va = g_vagg + (size_t)n * 9;
#pragma unroll
    for (int i = 0; i < 9; i++) vp[i] += va[i] * inv;
}

__global__ void write_out(float* __restrict__ out) {
    int i = blockIdx.x * blockDim.x + threadIdx.x;
    int stride = gridDim.x * blockDim.x;
    for (int k = i; k < N_NODES * SD; k += stride) out[k] = g_s[k];
    for (int k = i; k < N_NODES * VD * 3; k += stride) out[N_NODES * SD + k] = g_v[k];
}

// ---------------- launch ----------------
extern "C" void kernel_launch(void* const* d_in, const int* in_sizes, int n_in,
                              void* d_out, int out_size) {
    const float* s   = (const float*)d_in[0];
    const float* v   = (const float*)d_in[1];
    const int*   ei  = (const int*)d_in[2];
    const float* d   = (const float*)d_in[3];
    const float* r   = (const float*)d_in[4];
    const float* W1  = (const float*)d_in[5];
    const float* b1  = (const float*)d_in[6];
    const float* W2  = (const float*)d_in[7];
    const float* b2  = (const float*)d_in[8];
    const float* W3  = (const float*)d_in[9];
    const float* b3  = (const float*)d_in[10];
    const float* Wn1 = (const float*)d_in[11];
    const float* bn1 = (const float*)d_in[12];
    const float* Wn2 = (const float*)d_in[13];
    const float* bn2 = (const float*)d_in[14];
    float* out = (float*)d_out;

    const int pre_smem  = (256 * HID + HID) * 4;
    const int edge_smem = (HID * HID * 2 + HID * 8 + HID + HID + 8) * 4;
    const int node_smem = (SD * HID + HID * SD + HID + SD + HID) * 4;
    cudaFuncSetAttribute(precompute_h, cudaFuncAttributeMaxDynamicSharedMemorySize, pre_smem);
    cudaFuncSetAttribute(edge_kernel, cudaFuncAttributeMaxDynamicSharedMemorySize, edge_smem);
    cudaFuncSetAttribute(node_kernel, cudaFuncAttributeMaxDynamicSharedMemorySize, node_smem);

    init_state<<<1024, 256>>>(s, v);
    prep_edges<<<(N_EDGES + 255) / 256, 256>>>(ei, d);
    compute_inv<<<(N_NODES + 255) / 256, 256>>>();
    fuse_w3_all<<<(DEPTH * (HID * HID + HID) + 255) / 256, 256>>>(W3, Wn1, b3);

    for (int l = 0; l < DEPTH; l++) {
        precompute_h<<<(N_NODES + 255) / 256, 256, pre_smem>>>(W1, b1, l);
        zero_agg<<<1024, 256>>>();
        edge_kernel<<<(N_EDGES + 255) / 256, 256, edge_smem>>>(ei, d, r, W1, W2, b2, W3, b3, l);
        node_kernel<<<(N_NODES + 255) / 256, 256, node_smem>>>(Wn1, bn1, Wn2, bn2, l);
    }
    write_out<<<1024, 256>>>(out);
}

// round 12
// speedup vs baseline: 1.8234x; 1.0674x over previous
#include <cuda_runtime.h>
#include <cstdint>

#define N_NODES 50000
#define N_EDGES 500000
#define SD 128
#define VD 3
#define HID 64
#define DEPTH 4
#define CUTOFF 5.0f

// ---------------- scratch state ----------------
__device__ float g_s[N_NODES * SD];
__device__ float g_v[N_NODES * VD * 3];
__device__ float g_zagg[N_NODES * HID];    // scatter of z = C * (h2 @ Wz)
__device__ float g_vagg[N_NODES * VD * 3];
__device__ float g_cnt[N_NODES];
__device__ float g_inv[N_NODES];
__device__ float g_sumC[N_NODES];
__device__ float g_C[N_EDGES];
__device__ float g_ha[N_NODES * HID];      // s @ W1[0:128] + b1
__device__ float g_hb[N_NODES * HID];      // s @ W1[128:256]
__device__ float g_Wz[DEPTH * HID * HID];  // W3s @ Wn1b (all layers)
__device__ float g_bz[DEPTH * HID];        // b3s @ Wn1b

__device__ __forceinline__ float silu(float x) {
    return x / (1.0f + __expf(-x));
}

// ---------------- packed f32x2 helpers ----------------
__device__ __forceinline__ unsigned long long pack2(float x) {
    unsigned long long p;
    unsigned int u = __float_as_uint(x);
    asm("mov.b64 %0, {%1, %1};" : "=l"(p) : "r"(u));
    return p;
}
__device__ __forceinline__ void unpack2(unsigned long long p, float& lo, float& hi) {
    unsigned int a, b;
    asm("mov.b64 {%0, %1}, %2;" : "=r"(a), "=r"(b) : "l"(p));
    lo = __uint_as_float(a);
    hi = __uint_as_float(b);
}
__device__ __forceinline__ void fma2(unsigned long long& acc,
                                     unsigned long long a, unsigned long long b) {
    asm("fma.rn.f32x2 %0, %1, %2, %0;" : "+l"(acc) : "l"(a), "l"(b));
}
__device__ __forceinline__ unsigned long long mul2(unsigned long long a,
                                                   unsigned long long b) {
    unsigned long long d;
    asm("mul.rn.f32x2 %0, %1, %2;" : "=l"(d) : "l"(a), "l"(b));
    return d;
}

__device__ __forceinline__ void red_add4(float* p, float a, float b, float c, float d) {
    asm volatile("red.global.add.v4.f32 [%0], {%1,%2,%3,%4};"
                 :: "l"(p), "f"(a), "f"(b), "f"(c), "f"(d) : "memory");
}
__device__ __forceinline__ void red_add1(float* p, float a) {
    asm volatile("red.global.add.f32 [%0], %1;" :: "l"(p), "f"(a) : "memory");
}

// ---------------- prep kernels ----------------
__global__ void init_state(const float* __restrict__ s, const float* __restrict__ v) {
    int i = blockIdx.x * blockDim.x + threadIdx.x;
    int stride = gridDim.x * blockDim.x;
    for (int k = i; k < N_NODES * SD; k += stride) g_s[k] = s[k];
    for (int k = i; k < N_NODES * VD * 3; k += stride) g_v[k] = v[k];
    for (int k = i; k < N_NODES; k += stride) { g_cnt[k] = 0.0f; g_sumC[k] = 0.0f; }
}

__global__ void prep_edges(const int* __restrict__ ei, const float* __restrict__ d) {
    int e = blockIdx.x * blockDim.x + threadIdx.x;
    if (e >= N_EDGES) return;
    int dst = ei[e];
    float dd = d[e];
    float c = 0.5f * (cospif(dd * (1.0f / CUTOFF)) + 1.0f);
    c = (dd < CUTOFF) ? c : 0.0f;
    g_C[e] = c;
    red_add1(&g_cnt[dst], 1.0f);
    red_add1(&g_sumC[dst], c);
}

__global__ void compute_inv() {
    int n = blockIdx.x * blockDim.x + threadIdx.x;
    if (n < N_NODES) g_inv[n] = 1.0f / fmaxf(g_cnt[n], 1.0f);
}

__global__ void zero_agg() {
    int i = blockIdx.x * blockDim.x + threadIdx.x;
    int stride = gridDim.x * blockDim.x;
    for (int k = i; k < N_NODES * HID; k += stride) g_zagg[k] = 0.0f;
    for (int k = i; k < N_NODES * VD * 3; k += stride) g_vagg[k] = 0.0f;
}

// ---------------- all-layer weight fold: Wz = W3s @ Wn1b, bz = b3s @ Wn1b ----
__global__ void fuse_w3_all(const float* __restrict__ W3, const float* __restrict__ Wn1,
                            const float* __restrict__ b3) {
    int idx = blockIdx.x * 256 + threadIdx.x;
    const int per_layer = HID * HID + HID;
    int layer = idx / per_layer;
    if (layer >= DEPTH) return;
    int li = idx - layer * per_layer;
    const float* W3g = W3 + (size_t)layer * HID * 134;
    const float* Wb  = Wn1 + (size_t)layer * 2 * SD * HID + SD * HID; // rows 128..255
    if (li < HID * HID) {
        int k = li >> 6, n = li & 63;
        float acc = 0.0f;
        for (int j = 0; j < SD; j++) acc += W3g[k * 134 + j] * Wb[j * HID + n];
        g_Wz[layer * HID * HID + li] = acc;
    } else {
        int n = li - HID * HID;
        const float* b3g = b3 + layer * 134;
        float acc = 0.0f;
        for (int j = 0; j < SD; j++) acc += b3g[j] * Wb[j * HID + n];
        g_bz[layer * HID + n] = acc;
    }
}

// ---------------- per-node W1 precompute (128-thread blocks for occupancy) --
__global__ __launch_bounds__(128) void precompute_h(
    const float* __restrict__ W1, const float* __restrict__ b1, int layer)
{
    extern __shared__ float sm[];
    float* W1s = sm;              // 256*64
    float* b1s = W1s + 256 * HID; // 64

    const float* W1g = W1 + (size_t)layer * 257 * HID;
    for (int i = threadIdx.x; i < 256 * HID; i += 128) W1s[i] = W1g[i];
    if (threadIdx.x < HID) b1s[threadIdx.x] = b1[layer * HID + threadIdx.x];
    __syncthreads();

    int n = blockIdx.x * 128 + threadIdx.x;
    if (n >= N_NODES) return;

    const float4* xs = reinterpret_cast<const float4*>(g_s + (size_t)n * SD);

    // ---- ha ----
    unsigned long long acc[32];
    {
        const unsigned long long* bp = (const unsigned long long*)b1s;
#pragma unroll
        for (int q = 0; q < 32; q++) acc[q] = bp[q];
    }
#pragma unroll 4
    for (int kk = 0; kk < SD / 4; kk++) {
        float4 xv = xs[kk];
        float xr[4] = {xv.x, xv.y, xv.z, xv.w};
#pragma unroll
        for (int t = 0; t < 4; t++) {
            unsigned long long xk2 = pack2(xr[t]);
            const ulonglong2* wrow = reinterpret_cast<const ulonglong2*>(W1s + (kk * 4 + t) * HID);
#pragma unroll
            for (int q = 0; q < 16; q++) {
                ulonglong2 w = wrow[q];
                fma2(acc[2 * q + 0], xk2, w.x);
                fma2(acc[2 * q + 1], xk2, w.y);
            }
        }
    }
    {
        float* hap = g_ha + (size_t)n * HID;
#pragma unroll
        for (int q = 0; q < 32; q++) {
            float lo, hi;
            unpack2(acc[q], lo, hi);
            hap[2 * q + 0] = lo;
            hap[2 * q + 1] = hi;
        }
    }

    // ---- hb ----
#pragma unroll
    for (int q = 0; q < 32; q++) acc[q] = 0ULL;
#pragma unroll 4
    for (int kk = 0; kk < SD / 4; kk++) {
        float4 xv = xs[kk];
        float xr[4] = {xv.x, xv.y, xv.z, xv.w};
#pragma unroll
        for (int t = 0; t < 4; t++) {
            unsigned long long xk2 = pack2(xr[t]);
            const ulonglong2* wrow = reinterpret_cast<const ulonglong2*>(W1s + (SD + kk * 4 + t) * HID);
#pragma unroll
            for (int q = 0; q < 16; q++) {
                ulonglong2 w = wrow[q];
                fma2(acc[2 * q + 0], xk2, w.x);
                fma2(acc[2 * q + 1], xk2, w.y);
            }
        }
    }
    {
        float* hbp = g_hb + (size_t)n * HID;
#pragma unroll
        for (int q = 0; q < 32; q++) {
            float lo, hi;
            unpack2(acc[q], lo, hi);
            hbp[2 * q + 0] = lo;
            hbp[2 * q + 1] = hi;
        }
    }
}

// ---------------- fused edge MLP + scatter (per-thread, Wz-folded) ----------
__global__ __launch_bounds__(256, 2) void edge_kernel(
    const int* __restrict__ ei, const float* __restrict__ d, const float* __restrict__ r,
    const float* __restrict__ W1, const float* __restrict__ W2,
    const float* __restrict__ b2, const float* __restrict__ W3,
    const float* __restrict__ b3, int layer)
{
    extern __shared__ float sm[];
    float* W2s  = sm;                 // 64*64
    float* Wzs  = W2s + HID * HID;    // 64*64
    float* W3vs = Wzs + HID * HID;    // 64*8 (6 used, padded)
    float* wds  = W3vs + HID * 8;     // 64
    float* b2s  = wds + HID;          // 64
    float* b3vs = b2s + HID;          // 8

    const float* W2g = W2 + (size_t)layer * HID * HID;
    const float* W3g = W3 + (size_t)layer * HID * 134;
    const float* b3g = b3 + (size_t)layer * 134;
    const float* wdg = W1 + (size_t)layer * 257 * HID + 256 * HID;
    const float* Wzg = g_Wz + (size_t)layer * HID * HID;

    int tid = threadIdx.x;
    for (int i = tid; i < HID * HID; i += 256) { W2s[i] = W2g[i]; Wzs[i] = Wzg[i]; }
    for (int i = tid; i < HID * 6; i += 256) {
        int k = i / 6, j = i - k * 6;
        W3vs[k * 8 + j] = W3g[k * 134 + SD + j];
    }
    if (tid < HID) { wds[tid] = wdg[tid]; b2s[tid] = b2[layer * HID + tid]; }
    if (tid < 6) b3vs[tid] = b3g[SD + tid];
    __syncthreads();

    int e = blockIdx.x * 256 + tid;
    if (e >= N_EDGES) return;

    int dst = ei[e];
    int src = ei[N_EDGES + e];
    float C = g_C[e];
    float de = d[e];

    // ---- h1 = silu(ha[dst] + hb[src] + d*wd) ----
    float h1[HID];
    {
        const float4* ap = reinterpret_cast<const float4*>(g_ha + (size_t)dst * HID);
        const float4* bp = reinterpret_cast<const float4*>(g_hb + (size_t)src * HID);
        const float4* wp = reinterpret_cast<const float4*>(wds);
#pragma unroll
        for (int q = 0; q < HID / 4; q++) {
            float4 a = ap[q], b = bp[q], w = wp[q];
            h1[4 * q + 0] = silu(fmaf(de, w.x, a.x + b.x));
            h1[4 * q + 1] = silu(fmaf(de, w.y, a.y + b.y));
            h1[4 * q + 2] = silu(fmaf(de, w.z, a.z + b.z));
            h1[4 * q + 3] = silu(fmaf(de, w.w, a.w + b.w));
        }
    }

    // ---- h2 = silu(h1 @ W2 + b2), two 32-output halves ----
    float h2[HID];
#pragma unroll 1
    for (int half = 0; half < 2; half++) {
        unsigned long long acc[16];
        const unsigned long long* bp = (const unsigned long long*)(b2s + half * 32);
#pragma unroll
        for (int q = 0; q < 16; q++) acc[q] = bp[q];
#pragma unroll 4
        for (int k = 0; k < HID; k++) {
            unsigned long long hk2 = pack2(h1[k]);
            const ulonglong2* wrow = reinterpret_cast<const ulonglong2*>(W2s + k * HID + half * 32);
#pragma unroll
            for (int q = 0; q < 8; q++) {
                ulonglong2 w = wrow[q];
                fma2(acc[2 * q + 0], hk2, w.x);
                fma2(acc[2 * q + 1], hk2, w.y);
            }
        }
#pragma unroll
        for (int q = 0; q < 16; q++) {
            float lo, hi;
            unpack2(acc[q], lo, hi);
            h2[half * 32 + 2 * q + 0] = silu(lo);
            h2[half * 32 + 2 * q + 1] = silu(hi);
        }
    }

    // ---- z = h2 @ Wz (64 wide), scatter C*z; gv/gr fused into first half ----
    unsigned long long C2 = pack2(C);
    float* zbase = g_zagg + (size_t)dst * HID;

    unsigned long long g01 = ((const unsigned long long*)b3vs)[0];
    unsigned long long g23 = ((const unsigned long long*)b3vs)[1];
    unsigned long long g45 = ((const unsigned long long*)b3vs)[2];

#pragma unroll 1
    for (int half = 0; half < 2; half++) {
        unsigned long long acc[16];
#pragma unroll
        for (int q = 0; q < 16; q++) acc[q] = 0ULL;

        if (half == 0) {
#pragma unroll 4
            for (int k = 0; k < HID; k++) {
                unsigned long long hk2 = pack2(h2[k]);
                const ulonglong2* wrow = reinterpret_cast<const ulonglong2*>(Wzs + k * HID);
#pragma unroll
                for (int q = 0; q < 8; q++) {
                    ulonglong2 w = wrow[q];
                    fma2(acc[2 * q + 0], hk2, w.x);
                    fma2(acc[2 * q + 1], hk2, w.y);
                }
                const unsigned long long* gw = (const unsigned long long*)(W3vs + k * 8);
                fma2(g01, hk2, gw[0]);
                fma2(g23, hk2, gw[1]);
                fma2(g45, hk2, gw[2]);
            }
        } else {
#pragma unroll 4
            for (int k = 0; k < HID; k++) {
                unsigned long long hk2 = pack2(h2[k]);
                const ulonglong2* wrow = reinterpret_cast<const ulonglong2*>(Wzs + k * HID + 32);
#pragma unroll
                for (int q = 0; q < 8; q++) {
                    ulonglong2 w = wrow[q];
                    fma2(acc[2 * q + 0], hk2, w.x);
                    fma2(acc[2 * q + 1], hk2, w.y);
                }
            }
        }
#pragma unroll
        for (int q = 0; q < 8; q++) {
            unsigned long long p0 = mul2(acc[2 * q + 0], C2);
            unsigned long long p1 = mul2(acc[2 * q + 1], C2);
            float a0, a1, a2, a3;
            unpack2(p0, a0, a1);
            unpack2(p1, a2, a3);
            red_add4(zbase + half * 32 + q * 4, a0, a1, a2, a3);
        }
    }

    // ---- vector scatter ----
    float g6[6];
    unpack2(g01, g6[0], g6[1]);
    unpack2(g23, g6[2], g6[3]);
    unpack2(g45, g6[4], g6[5]);

    float rr0 = r[e * 3 + 0], rr1 = r[e * 3 + 1], rr2 = r[e * 3 + 2];
    const float* vs = g_v + (size_t)src * 9;
    float* vdp = g_vagg + (size_t)dst * 9;
#pragma unroll
    for (int a = 0; a < 3; a++) {
        float gva = g6[a] * C, gra = g6[3 + a] * C;
        red_add1(vdp + a * 3 + 0, vs[a * 3 + 0] * gva + rr0 * gra);
        red_add1(vdp + a * 3 + 1, vs[a * 3 + 1] * gva + rr1 * gra);
        red_add1(vdp + a * 3 + 2, vs[a * 3 + 2] * gva + rr2 * gra);
    }
}

// ---------------- fused node MLP + residual (128-thread blocks) -------------
__global__ __launch_bounds__(128) void node_kernel(
    const float* __restrict__ Wn1, const float* __restrict__ bn1,
    const float* __restrict__ Wn2, const float* __restrict__ bn2, int layer)
{
    extern __shared__ float sm[];
    float* W1s = sm;                 // 128*64 (Wn1 rows 0..127 only)
    float* W2s = W1s + SD * HID;     // 64*128
    float* b1s = W2s + HID * SD;     // 64
    float* b2s = b1s + HID;          // 128
    float* bzs = b2s + SD;           // 64

    const float* W1g = Wn1 + (size_t)layer * 2 * SD * HID;   // first 128 rows
    const float* W2g = Wn2 + (size_t)layer * HID * SD;
    for (int i = threadIdx.x; i < SD * HID; i += 128) W1s[i] = W1g[i];
    for (int i = threadIdx.x; i < HID * SD; i += 128) W2s[i] = W2g[i];
    if (threadIdx.x < HID) {
        b1s[threadIdx.x] = bn1[layer * HID + threadIdx.x];
        bzs[threadIdx.x] = g_bz[layer * HID + threadIdx.x];
    }
    if (threadIdx.x < SD) b2s[threadIdx.x] = bn2[layer * SD + threadIdx.x];
    __syncthreads();

    int n = blockIdx.x * 128 + threadIdx.x;
    if (n >= N_NODES) return;

    const float4* xs = reinterpret_cast<const float4*>(g_s + (size_t)n * SD);
    float sumC = g_sumC[n];
    const unsigned long long* zag = (const unsigned long long*)(g_zagg + (size_t)n * HID);

    // ---- u = silu(s@Wn1a + bn1 + zagg + sumC*bz) ----
    unsigned long long up[32];
    {
        const unsigned long long* bp = (const unsigned long long*)b1s;
#pragma unroll
        for (int q = 0; q < 32; q++) up[q] = bp[q];
    }
#pragma unroll 4
    for (int kk = 0; kk < SD / 4; kk++) {
        float4 xv = xs[kk];
        float xr[4] = {xv.x, xv.y, xv.z, xv.w};
#pragma unroll
        for (int t = 0; t < 4; t++) {
            unsigned long long xk2 = pack2(xr[t]);
            const ulonglong2* wrow = reinterpret_cast<const ulonglong2*>(W1s + (kk * 4 + t) * HID);
#pragma unroll
            for (int q = 0; q < 16; q++) {
                ulonglong2 w = wrow[q];
                fma2(up[2 * q + 0], xk2, w.x);
                fma2(up[2 * q + 1], xk2, w.y);
            }
        }
    }
    float u[HID];
#pragma unroll
    for (int q = 0; q < 32; q++) {
        float lo, hi;
        unpack2(up[q], lo, hi);
        float zl, zh;
        unpack2(zag[q], zl, zh);
        u[2 * q + 0] = silu(lo + zl + sumC * bzs[2 * q + 0]);
        u[2 * q + 1] = silu(hi + zh + sumC * bzs[2 * q + 1]);
    }

    float* sp = g_s + (size_t)n * SD;
#pragma unroll 1
    for (int c = 0; c < 4; c++) {
        unsigned long long acc[16];
        const unsigned long long* bp = (const unsigned long long*)(b2s + c * 32);
#pragma unroll
        for (int q = 0; q < 16; q++) acc[q] = bp[q];
#pragma unroll 4
        for (int k = 0; k < HID; k++) {
            unsigned long long hk2 = pack2(u[k]);
            const ulonglong2* wrow = reinterpret_cast<const ulonglong2*>(W2s + k * SD + c * 32);
#pragma unroll
            for (int q = 0; q < 8; q++) {
                ulonglong2 w = wrow[q];
                fma2(acc[2 * q + 0], hk2, w.x);
                fma2(acc[2 * q + 1], hk2, w.y);
            }
        }
#pragma unroll
        for (int q = 0; q < 16; q++) {
            float lo, hi;
            unpack2(acc[q], lo, hi);
            sp[c * 32 + 2 * q + 0] += lo;
            sp[c * 32 + 2 * q + 1] += hi;
        }
    }

    float inv = g_inv[n];
    float* vp = g_v + (size_t)n * 9;
    const float* va = g_vagg + (size_t)n * 9;
#pragma unroll
    for (int i = 0; i < 9; i++) vp[i] += va[i] * inv;
}

__global__ void write_out(float* __restrict__ out) {
    int i = blockIdx.x * blockDim.x + threadIdx.x;
    int stride = gridDim.x * blockDim.x;
    for (int k = i; k < N_NODES * SD; k += stride) out[k] = g_s[k];
    for (int k = i; k < N_NODES * VD * 3; k += stride) out[N_NODES * SD + k] = g_v[k];
}

// ---------------- launch ----------------
extern "C" void kernel_launch(void* const* d_in, const int* in_sizes, int n_in,
                              void* d_out, int out_size) {
    const float* s   = (const float*)d_in[0];
    const float* v   = (const float*)d_in[1];
    const int*   ei  = (const int*)d_in[2];
    const float* d   = (const float*)d_in[3];
    const float* r   = (const float*)d_in[4];
    const float* W1  = (const float*)d_in[5];
    const float* b1  = (const float*)d_in[6];
    const float* W2  = (const float*)d_in[7];
    const float* b2  = (const float*)d_in[8];
    const float* W3  = (const float*)d_in[9];
    const float* b3  = (const float*)d_in[10];
    const float* Wn1 = (const float*)d_in[11];
    const float* bn1 = (const float*)d_in[12];
    const float* Wn2 = (const float*)d_in[13];
    const float* bn2 = (const float*)d_in[14];
    float* out = (float*)d_out;

    const int pre_smem  = (256 * HID + HID) * 4;
    const int edge_smem = (HID * HID * 2 + HID * 8 + HID + HID + 8) * 4;
    const int node_smem = (SD * HID + HID * SD + HID + SD + HID) * 4;
    cudaFuncSetAttribute(precompute_h, cudaFuncAttributeMaxDynamicSharedMemorySize, pre_smem);
    cudaFuncSetAttribute(edge_kernel, cudaFuncAttributeMaxDynamicSharedMemorySize, edge_smem);
    cudaFuncSetAttribute(node_kernel, cudaFuncAttributeMaxDynamicSharedMemorySize, node_smem);

    init_state<<<1024, 256>>>(s, v);
    prep_edges<<<(N_EDGES + 255) / 256, 256>>>(ei, d);
    compute_inv<<<(N_NODES + 255) / 256, 256>>>();
    fuse_w3_all<<<(DEPTH * (HID * HID + HID) + 255) / 256, 256>>>(W3, Wn1, b3);

    for (int l = 0; l < DEPTH; l++) {
        precompute_h<<<(N_NODES + 127) / 128, 128, pre_smem>>>(W1, b1, l);
        zero_agg<<<1024, 256>>>();
        edge_kernel<<<(N_EDGES + 255) / 256, 256, edge_smem>>>(ei, d, r, W1, W2, b2, W3, b3, l);
        node_kernel<<<(N_NODES + 127) / 128, 128, node_smem>>>(Wn1, bn1, Wn2, bn2, l);
    }
    write_out<<<1024, 256>>>(out);
}